// round 3
// baseline (speedup 1.0000x reference)
#include <cuda_runtime.h>
#include <cuda_fp16.h>

#define N_NODES 100000
#define N_EDGES 500000
#define IN_DIM 16
#define HEADS 4
#define OUT_DIM 128
#define HC 512           // HEADS*OUT_DIM
#define NEG 0.2f

// Scratch (device globals: allocation-free per harness rules)
__device__ __half g_xl[(size_t)N_NODES * HC];    // 102.4 MB
__device__ int    g_counts[N_NODES];             // per-dst degree
__device__ int    g_row[N_NODES + 1];            // CSR row starts
__device__ int    g_cursor[N_NODES];             // fill cursors
__device__ int    g_srcs[N_EDGES];               // CSR column (src) array

__device__ __forceinline__ float lrelu(float v) { return v > 0.f ? v : NEG * v; }

// ---------------------------------------------------------------------------
// K1: x_l = X @ W_l + b_l, stored fp16. Thread owns 2 adjacent columns
// (half2 store); 128 nodes per 256-thread block.
// ---------------------------------------------------------------------------
__global__ __launch_bounds__(256) void proj_l_kernel(
    const float* __restrict__ X,
    const float* __restrict__ Wl, const float* __restrict__ bl)
{
    __shared__ float sx[128 * IN_DIM];
    const int c0 = threadIdx.x * 2;  // columns c0, c0+1
    float w0[IN_DIM], w1[IN_DIM];
#pragma unroll
    for (int k = 0; k < IN_DIM; k++) {
        w0[k] = Wl[k * HC + c0];
        w1[k] = Wl[k * HC + c0 + 1];
    }
    const float b0 = bl[c0], b1 = bl[c0 + 1];

    const int n0 = blockIdx.x * 128;
    const int nmax = min(128, N_NODES - n0);

    for (int i = threadIdx.x; i < nmax * IN_DIM; i += blockDim.x)
        sx[i] = X[(size_t)n0 * IN_DIM + i];
    __syncthreads();

    for (int n = 0; n < nmax; n++) {
        float a0 = b0, a1 = b1;
#pragma unroll
        for (int k = 0; k < IN_DIM; k++) {
            const float xv = sx[n * IN_DIM + k];
            a0 = fmaf(xv, w0[k], a0);
            a1 = fmaf(xv, w1[k], a1);
        }
        ((__half2*)g_xl)[((size_t)(n0 + n) * HC + c0) >> 1] =
            __floats2half2_rn(a0, a1);
    }
}

// ---------------------------------------------------------------------------
// CSR build: histogram -> single-block scan -> fill
// ---------------------------------------------------------------------------
__global__ __launch_bounds__(256) void hist_kernel(const int* __restrict__ idx)
{
    const int e = blockIdx.x * blockDim.x + threadIdx.x;
    if (e < N_EDGES) atomicAdd(&g_counts[idx[N_EDGES + e]], 1);
}

__global__ __launch_bounds__(1024) void scan_kernel()
{
    __shared__ int sp[1024];
    const int t = threadIdx.x;
    const int CH = (N_NODES + 1023) / 1024;  // 98
    const int base = t * CH;
    const int lim = min(CH, N_NODES - base);

    int sum = 0;
    for (int i = 0; i < lim; i++) sum += g_counts[base + i];
    sp[t] = sum;
    __syncthreads();
    // Hillis-Steele inclusive scan
    for (int off = 1; off < 1024; off <<= 1) {
        int v = (t >= off) ? sp[t - off] : 0;
        __syncthreads();
        sp[t] += v;
        __syncthreads();
    }
    int run = (t > 0) ? sp[t - 1] : 0;  // exclusive
    for (int i = 0; i < lim; i++) {
        g_row[base + i] = run;
        g_cursor[base + i] = run;
        run += g_counts[base + i];
    }
    if (t == 0) g_row[N_NODES] = N_EDGES;
}

__global__ __launch_bounds__(256) void fill_kernel(const int* __restrict__ idx)
{
    const int e = blockIdx.x * blockDim.x + threadIdx.x;
    if (e >= N_EDGES) return;
    const int dst = idx[N_EDGES + e];
    const int pos = atomicAdd(&g_cursor[dst], 1);
    g_srcs[pos] = idx[e];
}

// ---------------------------------------------------------------------------
// K2: node-centric fused GATv2. One warp per dst node.
//   xr = X[dst] @ W_r + b_r     (W_r in smem, computed in registers)
//   for each incoming edge: gather x_l[src] (fp16), score, exp, accumulate
//   out[dst] = acc / den + bias (single coalesced write; no atomics)
// ---------------------------------------------------------------------------
__global__ __launch_bounds__(256) void aggregate_kernel(
    const float* __restrict__ X,
    const float* __restrict__ Wr, const float* __restrict__ br,
    const float* __restrict__ att, const float* __restrict__ bias,
    float* __restrict__ out)
{
    __shared__ float sWr[IN_DIM * HC];  // 32 KB
    __shared__ float sbr[HC];           // 2 KB

    for (int i = threadIdx.x; i < IN_DIM * HC / 4; i += blockDim.x)
        ((float4*)sWr)[i] = ((const float4*)Wr)[i];
    for (int i = threadIdx.x; i < HC / 4; i += blockDim.x)
        ((float4*)sbr)[i] = ((const float4*)br)[i];
    __syncthreads();

    const int node = blockIdx.x * 8 + (threadIdx.x >> 5);
    if (node >= N_NODES) return;
    const int lane = threadIdx.x & 31;

    // X[node] row (broadcast loads)
    float xk[IN_DIM];
    {
        const float4* X4 = (const float4*)(X + (size_t)node * IN_DIM);
#pragma unroll
        for (int j = 0; j < 4; j++) {
            const float4 v = __ldg(&X4[j]);
            xk[4 * j + 0] = v.x; xk[4 * j + 1] = v.y;
            xk[4 * j + 2] = v.z; xk[4 * j + 3] = v.w;
        }
    }

    // xr[h][0..3] for columns h*128 + lane*4 .. +3
    float4 xr[HEADS];
#pragma unroll
    for (int h = 0; h < HEADS; h++)
        xr[h] = ((const float4*)sbr)[h * 32 + lane];
#pragma unroll
    for (int k = 0; k < IN_DIM; k++) {
        const float xv = xk[k];
#pragma unroll
        for (int h = 0; h < HEADS; h++) {
            const float4 w = ((const float4*)sWr)[k * (HC / 4) + h * 32 + lane];
            xr[h].x = fmaf(xv, w.x, xr[h].x);
            xr[h].y = fmaf(xv, w.y, xr[h].y);
            xr[h].z = fmaf(xv, w.z, xr[h].z);
            xr[h].w = fmaf(xv, w.w, xr[h].w);
        }
    }

    // attention weights for this lane's columns
    float4 aw[HEADS];
#pragma unroll
    for (int h = 0; h < HEADS; h++)
        aw[h] = __ldg(&((const float4*)att)[h * 32 + lane]);

    float4 acc[HEADS];
    float den[HEADS];
#pragma unroll
    for (int h = 0; h < HEADS; h++) {
        acc[h] = make_float4(0.f, 0.f, 0.f, 0.f);
        den[h] = 0.f;
    }

    const int eb = g_row[node];
    const int ee = g_row[node + 1];
    for (int j = eb; j < ee; j++) {
        const int src = g_srcs[j];  // lane-uniform
        const uint2* __restrict__ xlp = ((const uint2*)g_xl) + (size_t)src * 128;
#pragma unroll
        for (int h = 0; h < HEADS; h++) {
            const uint2 p = xlp[h * 32 + lane];
            const float2 f0 = __half22float2(*(const __half2*)&p.x);
            const float2 f1 = __half22float2(*(const __half2*)&p.y);

            float s = lrelu(f0.x + xr[h].x) * aw[h].x;
            s = fmaf(lrelu(f0.y + xr[h].y), aw[h].y, s);
            s = fmaf(lrelu(f1.x + xr[h].z), aw[h].z, s);
            s = fmaf(lrelu(f1.y + xr[h].w), aw[h].w, s);
#pragma unroll
            for (int off = 16; off > 0; off >>= 1)
                s += __shfl_xor_sync(0xffffffffu, s, off);

            // no max-subtraction: |e| is small; softmax ratio unchanged
            const float ex = __expf(s);
            acc[h].x = fmaf(ex, f0.x, acc[h].x);
            acc[h].y = fmaf(ex, f0.y, acc[h].y);
            acc[h].z = fmaf(ex, f1.x, acc[h].z);
            acc[h].w = fmaf(ex, f1.y, acc[h].w);
            den[h] += ex;
        }
    }

    float4* op = ((float4*)out) + (size_t)node * (HC / 4);
#pragma unroll
    for (int h = 0; h < HEADS; h++) {
        const float inv = (den[h] > 0.f) ? (1.0f / den[h]) : 0.f;
        const float4 b = __ldg(&((const float4*)bias)[h * 32 + lane]);
        float4 o;
        o.x = fmaf(acc[h].x, inv, b.x);
        o.y = fmaf(acc[h].y, inv, b.y);
        o.z = fmaf(acc[h].z, inv, b.z);
        o.w = fmaf(acc[h].w, inv, b.w);
        op[h * 32 + lane] = o;
    }
}

// ---------------------------------------------------------------------------
extern "C" void kernel_launch(void* const* d_in, const int* in_sizes, int n_in,
                              void* d_out, int out_size)
{
    const float* X    = (const float*)d_in[0];  // [N, 16]
    const int*   idx  = (const int*)  d_in[1];  // [2, E]
    const float* Wl   = (const float*)d_in[2];  // [16, 512]
    const float* bl   = (const float*)d_in[3];  // [512]
    const float* Wr   = (const float*)d_in[4];  // [16, 512]
    const float* br   = (const float*)d_in[5];  // [512]
    const float* att  = (const float*)d_in[6];  // [4, 128]
    const float* bias = (const float*)d_in[7];  // [512]
    float* out = (float*)d_out;                 // [N, 512]

    void* counts_ptr = nullptr;
    cudaGetSymbolAddress(&counts_ptr, g_counts);
    cudaMemsetAsync(counts_ptr, 0, N_NODES * sizeof(int), 0);

    proj_l_kernel<<<(N_NODES + 127) / 128, 256>>>(X, Wl, bl);
    hist_kernel<<<(N_EDGES + 255) / 256, 256>>>(idx);
    scan_kernel<<<1, 1024>>>();
    fill_kernel<<<(N_EDGES + 255) / 256, 256>>>(idx);
    aggregate_kernel<<<(N_NODES + 7) / 8, 256>>>(X, Wr, br, att, bias, out);
}

// round 4
// speedup vs baseline: 1.3623x; 1.3623x over previous
#include <cuda_runtime.h>
#include <cuda_fp16.h>

#define N_NODES 100000
#define N_EDGES 500000
#define IN_DIM 16
#define HEADS 4
#define OUT_DIM 128
#define HC 512           // HEADS*OUT_DIM
#define NEG 0.2f

// Scratch (device globals: allocation-free per harness rules)
__device__ __half g_xl[(size_t)N_NODES * HC];    // 102.4 MB
__device__ __half g_xr[(size_t)N_NODES * HC];    // 102.4 MB
__device__ float  g_ex[(size_t)N_EDGES * HEADS]; // ex per CSR slot, 8 MB
__device__ int    g_counts[N_NODES];
__device__ int    g_row[N_NODES + 1];
__device__ int    g_cursor[N_NODES];
__device__ int    g_srcs[N_EDGES];               // CSR: src per slot
__device__ int    g_dsts[N_EDGES];               // CSR: dst per slot

__device__ __forceinline__ float lrelu(float v) { return v > 0.f ? v : NEG * v; }

// packed f32x2 helpers (sm_103a; ptxas never auto-fuses these)
__device__ __forceinline__ unsigned long long pack2(float lo, float hi) {
    unsigned long long r;
    asm("mov.b64 %0, {%1, %2};" : "=l"(r) : "f"(lo), "f"(hi));
    return r;
}
__device__ __forceinline__ void unpack2(unsigned long long v, float& lo, float& hi) {
    asm("mov.b64 {%0, %1}, %2;" : "=f"(lo), "=f"(hi) : "l"(v));
}
__device__ __forceinline__ void ffma2(unsigned long long& d,
                                      unsigned long long a, unsigned long long b) {
    asm("fma.rn.f32x2 %0, %1, %2, %3;" : "=l"(d) : "l"(a), "l"(b), "l"(d));
}

// ---------------------------------------------------------------------------
// K1: x_l = X@W_l + b_l ; x_r = X@W_r + b_r, fp16 out, packed f32x2 FMA.
// Thread owns 2 adjacent columns; 128 nodes per 256-thread block.
// ---------------------------------------------------------------------------
__global__ __launch_bounds__(256) void proj_kernel(
    const float* __restrict__ X,
    const float* __restrict__ Wl, const float* __restrict__ bl,
    const float* __restrict__ Wr, const float* __restrict__ br)
{
    __shared__ float sx[128 * IN_DIM];
    const int c0 = threadIdx.x * 2;
    unsigned long long wl[IN_DIM], wr[IN_DIM];
#pragma unroll
    for (int k = 0; k < IN_DIM; k++) {
        wl[k] = pack2(Wl[k * HC + c0], Wl[k * HC + c0 + 1]);
        wr[k] = pack2(Wr[k * HC + c0], Wr[k * HC + c0 + 1]);
    }
    const unsigned long long bl2 = pack2(bl[c0], bl[c0 + 1]);
    const unsigned long long br2 = pack2(br[c0], br[c0 + 1]);

    const int n0 = blockIdx.x * 128;
    const int nmax = min(128, N_NODES - n0);

    for (int i = threadIdx.x; i < nmax * IN_DIM; i += blockDim.x)
        sx[i] = X[(size_t)n0 * IN_DIM + i];
    __syncthreads();

    for (int n = 0; n < nmax; n++) {
        unsigned long long al = bl2, ar = br2;
#pragma unroll
        for (int k = 0; k < IN_DIM; k++) {
            const float xv = sx[n * IN_DIM + k];
            const unsigned long long x2 = pack2(xv, xv);
            ffma2(al, x2, wl[k]);
            ffma2(ar, x2, wr[k]);
        }
        float l0, l1, r0, r1;
        unpack2(al, l0, l1);
        unpack2(ar, r0, r1);
        const size_t o = ((size_t)(n0 + n) * HC + c0) >> 1;
        ((__half2*)g_xl)[o] = __floats2half2_rn(l0, l1);
        ((__half2*)g_xr)[o] = __floats2half2_rn(r0, r1);
    }
}

// ---------------------------------------------------------------------------
// CSR build: histogram -> single-block scan -> fill (src + dst per slot)
// ---------------------------------------------------------------------------
__global__ __launch_bounds__(256) void hist_kernel(const int* __restrict__ idx)
{
    const int e = blockIdx.x * blockDim.x + threadIdx.x;
    if (e < N_EDGES) atomicAdd(&g_counts[idx[N_EDGES + e]], 1);
}

__global__ __launch_bounds__(1024) void scan_kernel()
{
    __shared__ int sp[1024];
    const int t = threadIdx.x;
    const int CH = (N_NODES + 1023) / 1024;
    const int base = t * CH;
    const int lim = min(CH, N_NODES - base);

    int sum = 0;
    for (int i = 0; i < lim; i++) sum += g_counts[base + i];
    sp[t] = sum;
    __syncthreads();
    for (int off = 1; off < 1024; off <<= 1) {
        int v = (t >= off) ? sp[t - off] : 0;
        __syncthreads();
        sp[t] += v;
        __syncthreads();
    }
    int run = (t > 0) ? sp[t - 1] : 0;
    for (int i = 0; i < lim; i++) {
        g_row[base + i] = run;
        g_cursor[base + i] = run;
        run += g_counts[base + i];
    }
    if (t == 0) g_row[N_NODES] = N_EDGES;
}

__global__ __launch_bounds__(256) void fill_kernel(const int* __restrict__ idx)
{
    const int e = blockIdx.x * blockDim.x + threadIdx.x;
    if (e >= N_EDGES) return;
    const int dst = idx[N_EDGES + e];
    const int pos = atomicAdd(&g_cursor[dst], 1);
    g_srcs[pos] = idx[e];
    g_dsts[pos] = dst;
}

// ---------------------------------------------------------------------------
// K2: edge-centric scores in CSR order (consecutive slots share dst -> L1/L2
// reuse of x_r row). One warp per CSR slot. Writes ex4 to g_ex[slot].
// No max-subtraction: scores are O(1), exp safe in fp32, softmax ratio exact.
// ---------------------------------------------------------------------------
__global__ __launch_bounds__(256) void score_kernel(const float* __restrict__ att)
{
    const int j = blockIdx.x * 8 + (threadIdx.x >> 5);
    if (j >= N_EDGES) return;
    const int lane = threadIdx.x & 31;
    const int src = g_srcs[j];
    const int dst = g_dsts[j];

    const uint2* __restrict__ xls = ((const uint2*)g_xl) + (size_t)src * 128;
    const uint2* __restrict__ xrs = ((const uint2*)g_xr) + (size_t)dst * 128;
    const float4* __restrict__ att4 = (const float4*)att;

    float eh[HEADS];
#pragma unroll
    for (int h = 0; h < HEADS; h++) {
        const uint2 ap = xls[h * 32 + lane];
        const uint2 bp = xrs[h * 32 + lane];
        const float2 a0 = __half22float2(*(const __half2*)&ap.x);
        const float2 a1 = __half22float2(*(const __half2*)&ap.y);
        const float2 b0 = __half22float2(*(const __half2*)&bp.x);
        const float2 b1 = __half22float2(*(const __half2*)&bp.y);

        const float4 w = __ldg(&att4[h * 32 + lane]);
        float s = lrelu(a0.x + b0.x) * w.x;
        s = fmaf(lrelu(a0.y + b0.y), w.y, s);
        s = fmaf(lrelu(a1.x + b1.x), w.z, s);
        s = fmaf(lrelu(a1.y + b1.y), w.w, s);
#pragma unroll
        for (int off = 16; off > 0; off >>= 1)
            s += __shfl_xor_sync(0xffffffffu, s, off);
        eh[h] = s;
    }

    if (lane == 0) {
        float4 ex;
        ex.x = __expf(eh[0]);
        ex.y = __expf(eh[1]);
        ex.z = __expf(eh[2]);
        ex.w = __expf(eh[3]);
        ((float4*)g_ex)[j] = ex;
    }
}

// ---------------------------------------------------------------------------
// K3: node-centric aggregate. One warp per node; loop over CSR slots:
// uniform ex4 + vector x_l gather + FMA. Registers only; single write with
// 1/den and bias fused. No atomics, no memset of out, no finalize pass.
// ---------------------------------------------------------------------------
__global__ __launch_bounds__(256) void aggregate_kernel(
    const float* __restrict__ bias, float* __restrict__ out)
{
    const int node = blockIdx.x * 8 + (threadIdx.x >> 5);
    if (node >= N_NODES) return;
    const int lane = threadIdx.x & 31;

    const int eb = g_row[node];
    const int ee = g_row[node + 1];

    float4 acc[HEADS];
#pragma unroll
    for (int h = 0; h < HEADS; h++) acc[h] = make_float4(0.f, 0.f, 0.f, 0.f);
    float4 den = make_float4(0.f, 0.f, 0.f, 0.f);

    for (int j = eb; j < ee; j++) {
        const int src = g_srcs[j];                       // lane-uniform
        const float4 ex = __ldg(&((const float4*)g_ex)[j]);
        const uint2* __restrict__ xlp = ((const uint2*)g_xl) + (size_t)src * 128;
#pragma unroll
        for (int h = 0; h < HEADS; h++) {
            const uint2 p = xlp[h * 32 + lane];
            const float2 f0 = __half22float2(*(const __half2*)&p.x);
            const float2 f1 = __half22float2(*(const __half2*)&p.y);
            const float s = (h == 0) ? ex.x : (h == 1) ? ex.y : (h == 2) ? ex.z : ex.w;
            acc[h].x = fmaf(s, f0.x, acc[h].x);
            acc[h].y = fmaf(s, f0.y, acc[h].y);
            acc[h].z = fmaf(s, f1.x, acc[h].z);
            acc[h].w = fmaf(s, f1.y, acc[h].w);
        }
        den.x += ex.x; den.y += ex.y; den.z += ex.z; den.w += ex.w;
    }

    const float invd[HEADS] = {
        den.x > 0.f ? 1.0f / den.x : 0.f,
        den.y > 0.f ? 1.0f / den.y : 0.f,
        den.z > 0.f ? 1.0f / den.z : 0.f,
        den.w > 0.f ? 1.0f / den.w : 0.f
    };

    float4* op = ((float4*)out) + (size_t)node * (HC / 4);
#pragma unroll
    for (int h = 0; h < HEADS; h++) {
        const float4 b = __ldg(&((const float4*)bias)[h * 32 + lane]);
        float4 o;
        o.x = fmaf(acc[h].x, invd[h], b.x);
        o.y = fmaf(acc[h].y, invd[h], b.y);
        o.z = fmaf(acc[h].z, invd[h], b.z);
        o.w = fmaf(acc[h].w, invd[h], b.w);
        op[h * 32 + lane] = o;
    }
}

// ---------------------------------------------------------------------------
extern "C" void kernel_launch(void* const* d_in, const int* in_sizes, int n_in,
                              void* d_out, int out_size)
{
    const float* X    = (const float*)d_in[0];  // [N, 16]
    const int*   idx  = (const int*)  d_in[1];  // [2, E]
    const float* Wl   = (const float*)d_in[2];  // [16, 512]
    const float* bl   = (const float*)d_in[3];  // [512]
    const float* Wr   = (const float*)d_in[4];  // [16, 512]
    const float* br   = (const float*)d_in[5];  // [512]
    const float* att  = (const float*)d_in[6];  // [4, 128]
    const float* bias = (const float*)d_in[7];  // [512]
    float* out = (float*)d_out;                 // [N, 512]

    void* counts_ptr = nullptr;
    cudaGetSymbolAddress(&counts_ptr, g_counts);
    cudaMemsetAsync(counts_ptr, 0, N_NODES * sizeof(int), 0);

    proj_kernel<<<(N_NODES + 127) / 128, 256>>>(X, Wl, bl, Wr, br);
    hist_kernel<<<(N_EDGES + 255) / 256, 256>>>(idx);
    scan_kernel<<<1, 1024>>>();
    fill_kernel<<<(N_EDGES + 255) / 256, 256>>>(idx);
    score_kernel<<<(N_EDGES + 7) / 8, 256>>>(att);
    aggregate_kernel<<<(N_NODES + 7) / 8, 256>>>(bias, out);
}